// round 8
// baseline (speedup 1.0000x reference)
#include <cuda_runtime.h>
#include <cuda_bf16.h>
#include <cstdint>

// ---------------- problem constants ----------------
static constexpr int N_ = 50000;
static constexpr int E_ = 600000;
static constexpr int G_ = 256;
static constexpr int D_ = 128;
static constexpr int L_ = 5;
static constexpr int V_ = 128;

static constexpr int MBLKS = (N_ + 127) / 128;   // 391

// ---------------- scratch (static device globals; no runtime alloc) --------
__device__ float d_h   [N_ * D_];
__device__ float d_hsum[N_ * D_];
__device__ float d_agg [N_ * D_];
__device__ float d_z1  [N_ * 2 * D_];
__device__ float d_hpre[N_ * D_];
__device__ float d_stats[L_ * 1024];
__device__ float d_sc1[2 * D_];
__device__ float d_sh1[2 * D_];
__device__ float d_sc2[D_];
__device__ float d_sh2[D_];
__device__ float d_pool[G_ * D_];
__device__ float d_cnt [G_];
__device__ float d_rep [G_ * D_];
__device__ float d_zf1 [G_ * 1024];
__device__ float d_zf2 [G_ * 1024];
__device__ float d_zf3 [G_ * 512];

// bf16 split weights (row-major W^T)
__device__ __nv_bfloat16 d_Wh[65536];       // W1^T [256,128] @0, W2^T [128,256] @32768
__device__ __nv_bfloat16 d_Wl[65536];

__device__ __forceinline__ float* buf(int id) {
    switch (id) {
        case 0:  return d_h;
        case 1:  return d_hsum;
        case 2:  return d_agg;
        case 3:  return d_z1;
        case 4:  return d_hpre;
        case 5:  return d_stats;
        case 10: return d_pool;
        case 11: return d_cnt;
        case 12: return d_rep;
        case 13: return d_zf1;
        case 14: return d_zf2;
        case 15: return d_zf3;
    }
    return nullptr;
}

// ---------------- PTX helpers ----------------
typedef unsigned long long u64;

__device__ __forceinline__ uint32_t smem_u32(const void* p) {
    uint32_t a;
    asm("{ .reg .u64 t; cvta.to.shared.u64 t, %1; cvt.u32.u64 %0, t; }" : "=r"(a) : "l"(p));
    return a;
}
__device__ __forceinline__ void mma_bf16(float* d, const uint32_t* a, const uint32_t* b) {
    asm volatile(
        "mma.sync.aligned.m16n8k16.row.col.f32.bf16.bf16.f32 "
        "{%0,%1,%2,%3}, {%4,%5,%6,%7}, {%8,%9}, {%0,%1,%2,%3};"
        : "+f"(d[0]), "+f"(d[1]), "+f"(d[2]), "+f"(d[3])
        : "r"(a[0]), "r"(a[1]), "r"(a[2]), "r"(a[3]), "r"(b[0]), "r"(b[1]));
}
__device__ __forceinline__ void ldmx4(uint32_t* r, uint32_t addr) {
    asm volatile("ldmatrix.sync.aligned.m8n8.x4.shared.b16 {%0,%1,%2,%3}, [%4];"
                 : "=r"(r[0]), "=r"(r[1]), "=r"(r[2]), "=r"(r[3]) : "r"(addr));
}

// split 8 floats into bf16 hi + lo packs
__device__ __forceinline__ void split8(const float* v, uint4& uh, uint4& ul) {
    __nv_bfloat16 h[8], l[8];
#pragma unroll
    for (int j = 0; j < 8; j++) {
        float x = v[j];
        __nv_bfloat16 hb = __float2bfloat16(x);
        h[j] = hb;
        l[j] = __float2bfloat16(x - __bfloat162float(hb));
    }
    uh = *reinterpret_cast<uint4*>(h);
    ul = *reinterpret_cast<uint4*>(l);
}

// f32x2 packed helpers (FC head SGEMM)
__device__ __forceinline__ u64 splat2(float x) {
    u64 r; asm("mov.b64 %0, {%1, %1};" : "=l"(r) : "f"(x)); return r;
}
__device__ __forceinline__ void fma2(u64& d, u64 a, u64 b) {
    asm("fma.rn.f32x2 %0, %1, %2, %0;" : "+l"(d) : "l"(a), "l"(b));
}
__device__ __forceinline__ void unpack2(u64 p, float& lo, float& hi) {
    asm("mov.b64 {%0, %1}, %2;" : "=f"(lo), "=f"(hi) : "l"(p));
}
__device__ __forceinline__ void red4(float* addr, float4 v) {
    asm volatile("red.global.add.v4.f32 [%0], {%1,%2,%3,%4};"
                 :: "l"(addr), "f"(v.x), "f"(v.y), "f"(v.z), "f"(v.w) : "memory");
}

// ---------------- small utility kernels ----------------
__global__ void k_zero(int id, int n) {
    int i = blockIdx.x * blockDim.x + threadIdx.x;
    if (i < n) buf(id)[i] = 0.f;
}

__global__ void k_atom(const int* __restrict__ x, const float* __restrict__ aemb,
                       const float* __restrict__ eps) {
    int i = blockIdx.x;
    int d = threadIdx.x;
    float v = 0.f;
#pragma unroll
    for (int f = 0; f < 9; f++) {
        int idx = x[i * 9 + f];
        v += aemb[((size_t)f * V_ + idx) * D_ + d];
    }
    d_h[(size_t)i * D_ + d]    = v;
    d_hsum[(size_t)i * D_ + d] = v;
    d_agg[(size_t)i * D_ + d]  = v * (1.f + eps[0]);
}

__global__ void k_edge(const int* __restrict__ ei, const int* __restrict__ ea,
                       const float* __restrict__ bond) {
    int e = blockIdx.x * (blockDim.x >> 5) + (threadIdx.x >> 5);
    if (e >= E_) return;
    int lane = threadIdx.x & 31;
    int src = ei[e];
    int dst = ei[E_ + e];
    int a0 = ea[e * 3 + 0], a1 = ea[e * 3 + 1], a2 = ea[e * 3 + 2];
    int d4 = lane * 4;
    float4 t0 = *reinterpret_cast<const float4*>(bond + ((size_t)0 * V_ + a0) * D_ + d4);
    float4 t1 = *reinterpret_cast<const float4*>(bond + ((size_t)1 * V_ + a1) * D_ + d4);
    float4 t2 = *reinterpret_cast<const float4*>(bond + ((size_t)2 * V_ + a2) * D_ + d4);
    float4 hv = *reinterpret_cast<const float4*>(d_h + (size_t)src * D_ + d4);
    float4 m;
    m.x = fmaxf(hv.x + t0.x + t1.x + t2.x, 0.f);
    m.y = fmaxf(hv.y + t0.y + t1.y + t2.y, 0.f);
    m.z = fmaxf(hv.z + t0.z + t1.z + t2.z, 0.f);
    m.w = fmaxf(hv.w + t0.w + t1.w + t2.w, 0.f);
    red4(d_agg + (size_t)dst * D_ + d4, m);
}

__global__ void k_finalize(int statOff, const float* __restrict__ g,
                           const float* __restrict__ b, int which, float invM) {
    int c = threadIdx.x;
    int C = blockDim.x;
    const float* st = d_stats + statOff;
    float mean = st[c] * invM;
    float var  = st[C + c] * invM - mean * mean;
    float is   = rsqrtf(var + 1e-5f);
    float sc   = g[c] * is;
    if (which == 0) { d_sc1[c] = sc; d_sh1[c] = b[c] - mean * sc; }
    else            { d_sc2[c] = sc; d_sh2[c] = b[c] - mean * sc; }
}

// h = act(hpre*sc2+sh2); hsum += h; next-layer agg seed OR final pool
__global__ void k_apply(int do_relu, const float* __restrict__ eps, int lnext,
                        const int* __restrict__ batch) {
    int i = blockIdx.x * blockDim.x + threadIdx.x;
    float4 p  = reinterpret_cast<const float4*>(d_hpre)[i];
    int c4 = i & 31;
    float4 sc = reinterpret_cast<const float4*>(d_sc2)[c4];
    float4 sh = reinterpret_cast<const float4*>(d_sh2)[c4];
    float4 y;
    y.x = fmaf(p.x, sc.x, sh.x);
    y.y = fmaf(p.y, sc.y, sh.y);
    y.z = fmaf(p.z, sc.z, sh.z);
    y.w = fmaf(p.w, sc.w, sh.w);
    if (do_relu) {
        y.x = fmaxf(y.x, 0.f); y.y = fmaxf(y.y, 0.f);
        y.z = fmaxf(y.z, 0.f); y.w = fmaxf(y.w, 0.f);
    }
    float4 hs = reinterpret_cast<const float4*>(d_hsum)[i];
    hs.x += y.x; hs.y += y.y; hs.z += y.z; hs.w += y.w;
    if (lnext < L_) {
        reinterpret_cast<float4*>(d_h)[i] = y;
        reinterpret_cast<float4*>(d_hsum)[i] = hs;
        float s = 1.f + eps[lnext];
        float4 o;
        o.x = y.x * s; o.y = y.y * s; o.z = y.z * s; o.w = y.w * s;
        reinterpret_cast<float4*>(d_agg)[i] = o;
    } else {
        // final layer: pool hsum directly (h/hsum never written back)
        int node = i >> 5;
        int q = i & 31;
        int g = batch[node];
        red4(d_pool + (size_t)g * D_ + q * 4, hs);
        if (q == 0) atomicAdd(&d_cnt[g], 1.f);
    }
}

__global__ void k_rep() {
    int i = blockIdx.x * blockDim.x + threadIdx.x;
    float c = d_cnt[i >> 7];
    d_rep[i] = d_pool[i] / fmaxf(c, 1.f);
}

__global__ void k_initbias(int id, const float* __restrict__ bias, int C, int n) {
    int i = blockIdx.x * blockDim.x + threadIdx.x;
    if (i < n) buf(id)[i] = bias[i % C];
}

__global__ void k_fc4(const float* __restrict__ w4, const float* __restrict__ b4,
                      float* __restrict__ out) {
    int g = blockIdx.x;
    int t = threadIdx.x;
    float acc = 0.f;
#pragma unroll
    for (int k = t; k < 512; k += 128)
        acc += fmaxf(d_zf3[(size_t)g * 512 + k], 0.f) * w4[k];
#pragma unroll
    for (int o = 16; o > 0; o >>= 1)
        acc += __shfl_down_sync(0xffffffffu, acc, o);
    __shared__ float sred[4];
    if ((t & 31) == 0) sred[t >> 5] = acc;
    __syncthreads();
    if (t == 0) out[g] = sred[0] + sred[1] + sred[2] + sred[3] + b4[0];
}

// W[K,Nc] -> W^T hi/lo [Nc,K] at element offset wBase
__global__ void k_cvtW(const float* __restrict__ W, int K, int Nc, int wBase) {
    int idx = blockIdx.x * blockDim.x + threadIdx.x;
    int total = Nc * (K >> 3);
    if (idx >= total) return;
    int n  = idx / (K >> 3);
    int k0 = (idx % (K >> 3)) << 3;
    float v[8];
#pragma unroll
    for (int j = 0; j < 8; j++) v[j] = W[(size_t)(k0 + j) * Nc + n];
    uint4 uh, ul;
    split8(v, uh, ul);
    size_t o = ((size_t)wBase + (size_t)n * K + k0) >> 3;
    reinterpret_cast<uint4*>(d_Wh)[o] = uh;
    reinterpret_cast<uint4*>(d_Wl)[o] = ul;
}

// ---------------- fused tensor-core GEMM (mma.sync, split bf16) ------------
// C[M,Nc] = xform(A_fp32[M,K]) @ W^T + bias; in-loader split to hi/lo bf16.
// XF: 0 = identity, 2 = relu(a*sc1[k]+sh1[k]).  STATS: column sum/sumsq of C.
// grid (Nc/128, MBLKS), 256 threads. CTA tile 128x128, warp 64x32, BK=32.
static constexpr int SSTR = 40;   // smem row stride in bf16 elems (80 B)

template <int XF, bool STATS>
__global__ __launch_bounds__(256)
void k_mma(int aId, int wBase, const float* __restrict__ bias, int cId,
           int M, int Nc, int K, int statOff) {
    __shared__ __nv_bfloat16 As_h[128 * SSTR];
    __shared__ __nv_bfloat16 As_l[128 * SSTR];
    __shared__ __nv_bfloat16 Bs_h[128 * SSTR];
    __shared__ __nv_bfloat16 Bs_l[128 * SSTR];
    __shared__ float s_st[256];

    const float* A = buf(aId);
    const int tid = threadIdx.x, lane = tid & 31, wid = tid >> 5;
    const int wm = wid >> 2, wn = wid & 3;           // 2 x 4 warp grid
    const int mblk = blockIdx.y, nblk = blockIdx.x;

    float acc[4][4][4];
#pragma unroll
    for (int a = 0; a < 4; a++)
#pragma unroll
        for (int b = 0; b < 4; b++)
#pragma unroll
            for (int c = 0; c < 4; c++) acc[a][b][c] = 0.f;

    const uint32_t sAh = smem_u32(As_h), sAl = smem_u32(As_l);
    const uint32_t sBh = smem_u32(Bs_h), sBl = smem_u32(Bs_l);

    const int aoffb = ((lane & 15) * SSTR + ((lane >> 4) << 3)) * 2;
    const int piece = lane >> 3;
    const int boffb = (((lane & 7) + ((piece >> 1) << 3)) * SSTR + ((piece & 1) << 3)) * 2;

    const int nChunks = K >> 5;
    for (int kc = 0; kc < nChunks; kc++) {
        // ---- global -> smem: A fp32 (+transform) split in registers; B pre-split
#pragma unroll
        for (int it = 0; it < 2; it++) {
            int idx = it * 256 + tid;
            int r = idx >> 2;
            int c8 = (idx & 3) << 3;
            int gr = mblk * 128 + r;
            int gc = kc * 32 + c8;
            int soff = r * SSTR + c8;
            float v[8];
#pragma unroll
            for (int j = 0; j < 8; j++) v[j] = 0.f;
            if (gr < M) {
                const float4* s = reinterpret_cast<const float4*>(A + (size_t)gr * K + gc);
                *reinterpret_cast<float4*>(v)     = s[0];
                *reinterpret_cast<float4*>(v + 4) = s[1];
            }
            if (XF == 2) {
                float4 sc0 = *reinterpret_cast<const float4*>(d_sc1 + gc);
                float4 sc1v = *reinterpret_cast<const float4*>(d_sc1 + gc + 4);
                float4 sh0 = *reinterpret_cast<const float4*>(d_sh1 + gc);
                float4 sh1v = *reinterpret_cast<const float4*>(d_sh1 + gc + 4);
                v[0] = fmaxf(fmaf(v[0], sc0.x, sh0.x), 0.f);
                v[1] = fmaxf(fmaf(v[1], sc0.y, sh0.y), 0.f);
                v[2] = fmaxf(fmaf(v[2], sc0.z, sh0.z), 0.f);
                v[3] = fmaxf(fmaf(v[3], sc0.w, sh0.w), 0.f);
                v[4] = fmaxf(fmaf(v[4], sc1v.x, sh1v.x), 0.f);
                v[5] = fmaxf(fmaf(v[5], sc1v.y, sh1v.y), 0.f);
                v[6] = fmaxf(fmaf(v[6], sc1v.z, sh1v.z), 0.f);
                v[7] = fmaxf(fmaf(v[7], sc1v.w, sh1v.w), 0.f);
            }
            uint4 uh, ul;
            split8(v, uh, ul);
            *reinterpret_cast<uint4*>(&As_h[soff]) = uh;
            *reinterpret_cast<uint4*>(&As_l[soff]) = ul;
            size_t boff = (size_t)wBase + (size_t)(nblk * 128 + r) * K + gc;
            *reinterpret_cast<uint4*>(&Bs_h[soff]) = *reinterpret_cast<const uint4*>(d_Wh + boff);
            *reinterpret_cast<uint4*>(&Bs_l[soff]) = *reinterpret_cast<const uint4*>(d_Wl + boff);
        }
        __syncthreads();

#pragma unroll
        for (int ks = 0; ks < 2; ks++) {
            const int kb = ks * 32;
            uint32_t a_h[4][4], a_l[4][4], b_h[4][2], b_l[4][2];
#pragma unroll
            for (int mi = 0; mi < 4; mi++) {
                int off = aoffb + kb + (wm * 64 + mi * 16) * (SSTR * 2);
                ldmx4(a_h[mi], sAh + off);
                ldmx4(a_l[mi], sAl + off);
            }
#pragma unroll
            for (int nj = 0; nj < 2; nj++) {
                int off = boffb + kb + (wn * 32 + nj * 16) * (SSTR * 2);
                uint32_t r4[4];
                ldmx4(r4, sBh + off);
                b_h[nj * 2][0] = r4[0]; b_h[nj * 2][1] = r4[1];
                b_h[nj * 2 + 1][0] = r4[2]; b_h[nj * 2 + 1][1] = r4[3];
                ldmx4(r4, sBl + off);
                b_l[nj * 2][0] = r4[0]; b_l[nj * 2][1] = r4[1];
                b_l[nj * 2 + 1][0] = r4[2]; b_l[nj * 2 + 1][1] = r4[3];
            }
#pragma unroll
            for (int mi = 0; mi < 4; mi++)
#pragma unroll
                for (int ni = 0; ni < 4; ni++) {
                    mma_bf16(acc[mi][ni], a_h[mi], b_h[ni]);
                    mma_bf16(acc[mi][ni], a_h[mi], b_l[ni]);
                    mma_bf16(acc[mi][ni], a_l[mi], b_h[ni]);
                }
        }
        __syncthreads();
    }

    // ---- epilogue: bias + store + optional fused column stats ----
    float* C = buf(cId);
    float st_s[8], st_q[8];
#pragma unroll
    for (int j = 0; j < 8; j++) { st_s[j] = 0.f; st_q[j] = 0.f; }

#pragma unroll
    for (int mi = 0; mi < 4; mi++) {
        int row0 = mblk * 128 + wm * 64 + mi * 16 + (lane >> 2);
#pragma unroll
        for (int ni = 0; ni < 4; ni++) {
            int col = nblk * 128 + wn * 32 + ni * 8 + ((lane & 3) << 1);
            float b0 = bias[col], b1 = bias[col + 1];
            float v0 = acc[mi][ni][0] + b0, v1 = acc[mi][ni][1] + b1;
            float v2 = acc[mi][ni][2] + b0, v3 = acc[mi][ni][3] + b1;
            if (row0 < M) {
                *reinterpret_cast<float2*>(&C[(size_t)row0 * Nc + col]) = make_float2(v0, v1);
                if (STATS) {
                    st_s[ni * 2]     += v0; st_q[ni * 2]     += v0 * v0;
                    st_s[ni * 2 + 1] += v1; st_q[ni * 2 + 1] += v1 * v1;
                }
            }
            if (row0 + 8 < M) {
                *reinterpret_cast<float2*>(&C[(size_t)(row0 + 8) * Nc + col]) = make_float2(v2, v3);
                if (STATS) {
                    st_s[ni * 2]     += v2; st_q[ni * 2]     += v2 * v2;
                    st_s[ni * 2 + 1] += v3; st_q[ni * 2 + 1] += v3 * v3;
                }
            }
        }
    }

    if constexpr (STATS) {
        s_st[tid] = 0.f;
        __syncthreads();
#pragma unroll
        for (int j = 0; j < 8; j++) {
            int colLocal = wn * 32 + (j >> 1) * 8 + ((lane & 3) << 1) + (j & 1);
            atomicAdd(&s_st[colLocal], st_s[j]);
            atomicAdd(&s_st[128 + colLocal], st_q[j]);
        }
        __syncthreads();
        if (tid < 128) {
            atomicAdd(&d_stats[statOff + nblk * 128 + tid], s_st[tid]);
            atomicAdd(&d_stats[statOff + Nc + nblk * 128 + tid], s_st[128 + tid]);
        }
    }
}

// ---------------- FFMA2 SGEMM (FC head only) ----------------
template <int BM, int BN, int BK, int TM, int TN, int XF, bool ATOMIC>
__launch_bounds__((BM / TM) * (BN / TN))
__global__ void k_sgemm(int aId, const float* __restrict__ W,
                        const float* __restrict__ bias, int cId,
                        int M, int K, int Nc, int kLen) {
    constexpr int THREADS = (BM / TM) * (BN / TN);
    constexpr int PAD = 4;
    __shared__ float As[BK][BM + PAD];
    __shared__ float Ws[BK][BN];

    const float* A = buf(aId);
    float* C = buf(cId);

    const int tid  = threadIdx.x;
    const int tcol = tid % (BN / TN);
    const int trow = tid / (BN / TN);
    const int rowBase = blockIdx.y * BM;
    const int colBase = blockIdx.x * BN;
    const int kStart  = blockIdx.z * kLen;

    u64 acc2[TM / 2][TN];
#pragma unroll
    for (int i = 0; i < TM / 2; i++)
#pragma unroll
        for (int j = 0; j < TN; j++) acc2[i][j] = 0ull;

    constexpr int AROWS_PER   = (BM * BK) / THREADS;
    constexpr int AROW_STRIDE = THREADS / BK;
    constexpr int WROWS_PER   = (BK * BN) / THREADS;
    constexpr int WROW_STRIDE = THREADS / BN;

    const int aCol = tid % BK;
    const int aRow = tid / BK;
    const int wCol = tid % BN;
    const int wRow = tid / BN;

    for (int k0 = kStart; k0 < kStart + kLen; k0 += BK) {
        const int kk = k0 + aCol;
#pragma unroll
        for (int r = 0; r < AROWS_PER; r++) {
            int row = rowBase + aRow + r * AROW_STRIDE;
            float v = (row < M) ? A[(size_t)row * K + kk] : 0.f;
            if (XF == 1) v = fmaxf(v, 0.f);
            As[aCol][aRow + r * AROW_STRIDE] = v;
        }
#pragma unroll
        for (int r = 0; r < WROWS_PER; r++) {
            Ws[wRow + r * WROW_STRIDE][wCol] =
                W[(size_t)(k0 + wRow + r * WROW_STRIDE) * Nc + colBase + wCol];
        }
        __syncthreads();
#pragma unroll
        for (int kq = 0; kq < BK; kq++) {
            u64 a2[TM / 2];
            const u64* ap = reinterpret_cast<const u64*>(&As[kq][trow * TM]);
#pragma unroll
            for (int i = 0; i < TM / 2; i++) a2[i] = ap[i];
            float4 wv = *reinterpret_cast<const float4*>(&Ws[kq][tcol * TN]);
            float wf[4] = {wv.x, wv.y, wv.z, wv.w};
#pragma unroll
            for (int j = 0; j < TN; j++) {
                u64 wp = splat2(wf[j]);
#pragma unroll
                for (int i = 0; i < TM / 2; i++) fma2(acc2[i][j], a2[i], wp);
            }
        }
        __syncthreads();
    }

#pragma unroll
    for (int i = 0; i < TM / 2; i++) {
        int row0 = rowBase + trow * TM + 2 * i;
        float lo[TN], hi[TN];
#pragma unroll
        for (int j = 0; j < TN; j++) unpack2(acc2[i][j], lo[j], hi[j]);
        int col0 = colBase + tcol * TN;
        if (row0 < M) {
#pragma unroll
            for (int j = 0; j < TN; j++) atomicAdd(&C[(size_t)row0 * Nc + col0 + j], lo[j]);
        }
        if (row0 + 1 < M) {
#pragma unroll
            for (int j = 0; j < TN; j++) atomicAdd(&C[(size_t)(row0 + 1) * Nc + col0 + j], hi[j]);
        }
    }
}

// ---------------- launch ----------------
extern "C" void kernel_launch(void* const* d_in, const int* in_sizes, int n_in,
                              void* d_out, int out_size) {
    const int*   x        = (const int*)  d_in[0];
    const int*   ei       = (const int*)  d_in[1];
    const int*   ea       = (const int*)  d_in[2];
    const int*   batch    = (const int*)  d_in[3];
    const float* atom_emb = (const float*)d_in[4];
    const float* bond_emb = (const float*)d_in[5];
    const float* eps      = (const float*)d_in[6];
    const float* W1       = (const float*)d_in[7];
    const float* b1       = (const float*)d_in[8];
    const float* g1       = (const float*)d_in[9];
    const float* be1      = (const float*)d_in[10];
    const float* W2       = (const float*)d_in[11];
    const float* b2       = (const float*)d_in[12];
    const float* bn_g     = (const float*)d_in[13];
    const float* bn_b     = (const float*)d_in[14];
    const float* fcW1     = (const float*)d_in[15];
    const float* fcb1     = (const float*)d_in[16];
    const float* fcW2     = (const float*)d_in[17];
    const float* fcb2     = (const float*)d_in[18];
    const float* fcW3     = (const float*)d_in[19];
    const float* fcb3     = (const float*)d_in[20];
    const float* fcW4     = (const float*)d_in[21];
    const float* fcb4     = (const float*)d_in[22];
    float* out = (float*)d_out;

    const float invN = 1.f / (float)N_;

    // zero accumulators
    k_zero<<<(L_ * 1024 + 255) / 256, 256>>>(5, L_ * 1024);
    k_zero<<<(G_ * D_ + 255) / 256, 256>>>(10, G_ * D_);
    k_zero<<<1, 256>>>(11, G_);

    // weight split/transpose (shared across layers)
    k_cvtW<<<(256 * 16 + 255) / 256, 256>>>(W1, 128, 256, 0);
    k_cvtW<<<(128 * 32 + 255) / 256, 256>>>(W2, 256, 128, 32768);

    // atom encoder (seeds agg for layer 0)
    k_atom<<<N_, 128>>>(x, atom_emb, eps);

    const int vec = N_ * D_ / 4;
    for (int l = 0; l < L_; l++) {
        k_edge<<<E_ / 8, 256>>>(ei, ea, bond_emb + (size_t)l * 3 * V_ * D_);

        // GEMM1 (fused split + stats): z1 = agg @ W1 + b1  [N,128]x[128,256]
        k_mma<0, true><<<dim3(2, MBLKS), 256>>>(2, 0, b1, 3, N_, 256, 128, l * 1024);
        k_finalize<<<1, 256>>>(l * 1024, g1, be1, 0, invN);

        // GEMM2 (fused BN+relu+split + stats): hpre = relu(bn(z1)) @ W2 + b2
        k_mma<2, true><<<dim3(1, MBLKS), 256>>>(3, 32768, b2, 4, N_, 128, 256, l * 1024 + 512);
        k_finalize<<<1, 128>>>(l * 1024 + 512, bn_g + l * D_, bn_b + l * D_, 1, invN);

        // h = act(bn(hpre)); hsum += h; agg seed (or final pool on last layer)
        k_apply<<<vec / 256, 256>>>(l < L_ - 1 ? 1 : 0, eps, l + 1, batch);
    }

    // readout
    k_rep<<<(G_ * D_) / 256, 256>>>();

    // FC head (FFMA2 SGEMM, split-K atomics; relu on A-load of next GEMM)
    k_initbias<<<(G_ * 1024) / 256, 256>>>(13, fcb1, 1024, G_ * 1024);
    k_sgemm<64, 64, 16, 4, 4, 0, true>
        <<<dim3(1024 / 64, G_ / 64, 1), 256>>>(12, fcW1, nullptr, 13, G_, 128, 1024, 128);

    k_initbias<<<(G_ * 1024) / 256, 256>>>(14, fcb2, 1024, G_ * 1024);
    k_sgemm<64, 64, 16, 4, 4, 1, true>
        <<<dim3(1024 / 64, G_ / 64, 8), 256>>>(13, fcW2, nullptr, 14, G_, 1024, 1024, 128);

    k_initbias<<<(G_ * 512) / 256, 256>>>(15, fcb3, 512, G_ * 512);
    k_sgemm<64, 64, 16, 4, 4, 1, true>
        <<<dim3(512 / 64, G_ / 64, 8), 256>>>(14, fcW3, nullptr, 15, G_, 1024, 512, 128);

    k_fc4<<<G_, 128>>>(fcW4, fcb4, out);
}

// round 9
// speedup vs baseline: 1.0065x; 1.0065x over previous
#include <cuda_runtime.h>
#include <cuda_bf16.h>
#include <cstdint>

// ---------------- problem constants ----------------
static constexpr int N_ = 50000;
static constexpr int E_ = 600000;
static constexpr int G_ = 256;
static constexpr int D_ = 128;
static constexpr int L_ = 5;
static constexpr int V_ = 128;

static constexpr int MBLKS = (N_ + 127) / 128;   // 391

// ---------------- scratch (static device globals; no runtime alloc) --------
__device__ float d_h   [N_ * D_];     // only layer-0 input (atom encoder output)
__device__ float d_hsum[N_ * D_];
__device__ float d_agg [N_ * D_];
__device__ float d_z1  [N_ * 2 * D_];
__device__ float d_hpre[N_ * D_];
__device__ float d_stats[L_ * 1024];
__device__ float d_sc2[D_];
__device__ float d_sh2[D_];
__device__ float d_pool[G_ * D_];
__device__ float d_cnt [G_];
__device__ float d_rep [G_ * D_];
__device__ float d_zf1 [G_ * 1024];
__device__ float d_zf2 [G_ * 1024];
__device__ float d_zf3 [G_ * 512];

// bf16 split weights (row-major W^T)
__device__ __nv_bfloat16 d_Wh[65536];       // W1^T [256,128] @0, W2^T [128,256] @32768
__device__ __nv_bfloat16 d_Wl[65536];

__device__ __forceinline__ float* buf(int id) {
    switch (id) {
        case 0:  return d_h;
        case 1:  return d_hsum;
        case 2:  return d_agg;
        case 3:  return d_z1;
        case 4:  return d_hpre;
        case 5:  return d_stats;
        case 10: return d_pool;
        case 11: return d_cnt;
        case 12: return d_rep;
        case 13: return d_zf1;
        case 14: return d_zf2;
        case 15: return d_zf3;
    }
    return nullptr;
}

// ---------------- PTX helpers ----------------
typedef unsigned long long u64;

__device__ __forceinline__ uint32_t smem_u32(const void* p) {
    uint32_t a;
    asm("{ .reg .u64 t; cvta.to.shared.u64 t, %1; cvt.u32.u64 %0, t; }" : "=r"(a) : "l"(p));
    return a;
}
__device__ __forceinline__ void mma_bf16(float* d, const uint32_t* a, const uint32_t* b) {
    asm volatile(
        "mma.sync.aligned.m16n8k16.row.col.f32.bf16.bf16.f32 "
        "{%0,%1,%2,%3}, {%4,%5,%6,%7}, {%8,%9}, {%0,%1,%2,%3};"
        : "+f"(d[0]), "+f"(d[1]), "+f"(d[2]), "+f"(d[3])
        : "r"(a[0]), "r"(a[1]), "r"(a[2]), "r"(a[3]), "r"(b[0]), "r"(b[1]));
}
__device__ __forceinline__ void ldmx4(uint32_t* r, uint32_t addr) {
    asm volatile("ldmatrix.sync.aligned.m8n8.x4.shared.b16 {%0,%1,%2,%3}, [%4];"
                 : "=r"(r[0]), "=r"(r[1]), "=r"(r[2]), "=r"(r[3]) : "r"(addr));
}

// split 8 floats into bf16 hi + lo packs
__device__ __forceinline__ void split8(const float* v, uint4& uh, uint4& ul) {
    __nv_bfloat16 h[8], l[8];
#pragma unroll
    for (int j = 0; j < 8; j++) {
        float x = v[j];
        __nv_bfloat16 hb = __float2bfloat16(x);
        h[j] = hb;
        l[j] = __float2bfloat16(x - __bfloat162float(hb));
    }
    uh = *reinterpret_cast<uint4*>(h);
    ul = *reinterpret_cast<uint4*>(l);
}

// f32x2 packed helpers (FC head SGEMM)
__device__ __forceinline__ u64 splat2(float x) {
    u64 r; asm("mov.b64 %0, {%1, %1};" : "=l"(r) : "f"(x)); return r;
}
__device__ __forceinline__ void fma2(u64& d, u64 a, u64 b) {
    asm("fma.rn.f32x2 %0, %1, %2, %0;" : "+l"(d) : "l"(a), "l"(b));
}
__device__ __forceinline__ void unpack2(u64 p, float& lo, float& hi) {
    asm("mov.b64 {%0, %1}, %2;" : "=f"(lo), "=f"(hi) : "l"(p));
}
__device__ __forceinline__ void red4(float* addr, float4 v) {
    asm volatile("red.global.add.v4.f32 [%0], {%1,%2,%3,%4};"
                 :: "l"(addr), "f"(v.x), "f"(v.y), "f"(v.z), "f"(v.w) : "memory");
}

// ---------------- setup kernels ----------------
// zero stats + pool + cnt in one launch
__global__ void k_zero_all() {
    int i = blockIdx.x * blockDim.x + threadIdx.x;
    if (i < L_ * 1024)                  d_stats[i] = 0.f;
    else if (i < L_ * 1024 + G_ * D_)   d_pool[i - L_ * 1024] = 0.f;
    else if (i < L_ * 1024 + G_ * D_ + G_) d_cnt[i - L_ * 1024 - G_ * D_] = 0.f;
}

// both weights split/transposed in one launch
__global__ void k_cvtW2(const float* __restrict__ W1, const float* __restrict__ W2) {
    int idx = blockIdx.x * blockDim.x + threadIdx.x;
    const float* W; int K, Nc, wBase;
    if (idx < 4096)      { W = W1; K = 128; Nc = 256; wBase = 0; }
    else if (idx < 8192) { W = W2; K = 256; Nc = 128; wBase = 32768; idx -= 4096; }
    else return;
    int n  = idx / (K >> 3);
    int k0 = (idx % (K >> 3)) << 3;
    float v[8];
#pragma unroll
    for (int j = 0; j < 8; j++) v[j] = W[(size_t)(k0 + j) * Nc + n];
    uint4 uh, ul;
    split8(v, uh, ul);
    size_t o = ((size_t)wBase + (size_t)n * K + k0) >> 3;
    reinterpret_cast<uint4*>(d_Wh)[o] = uh;
    reinterpret_cast<uint4*>(d_Wl)[o] = ul;
}

__global__ void k_atom(const int* __restrict__ x, const float* __restrict__ aemb,
                       const float* __restrict__ eps) {
    int i = blockIdx.x;
    int d = threadIdx.x;
    float v = 0.f;
#pragma unroll
    for (int f = 0; f < 9; f++) {
        int idx = x[i * 9 + f];
        v += aemb[((size_t)f * V_ + idx) * D_ + d];
    }
    d_h[(size_t)i * D_ + d]    = v;
    d_hsum[(size_t)i * D_ + d] = v;
    d_agg[(size_t)i * D_ + d]  = v * (1.f + eps[0]);
}

// per-edge scatter. useH=1: gather d_h (layer 0). useH=0: gather d_hpre and
// recompute h = relu(hpre*sc2+sh2) on the fly (sc2/sh2 persisted by k_apply).
__global__ void k_edge(const int* __restrict__ ei, const int* __restrict__ ea,
                       const float* __restrict__ bond, int useH) {
    int e = blockIdx.x * (blockDim.x >> 5) + (threadIdx.x >> 5);
    if (e >= E_) return;
    int lane = threadIdx.x & 31;
    int src = ei[e];
    int dst = ei[E_ + e];
    int a0 = ea[e * 3 + 0], a1 = ea[e * 3 + 1], a2 = ea[e * 3 + 2];
    int d4 = lane * 4;
    float4 t0 = *reinterpret_cast<const float4*>(bond + ((size_t)0 * V_ + a0) * D_ + d4);
    float4 t1 = *reinterpret_cast<const float4*>(bond + ((size_t)1 * V_ + a1) * D_ + d4);
    float4 t2 = *reinterpret_cast<const float4*>(bond + ((size_t)2 * V_ + a2) * D_ + d4);
    float4 hv;
    if (useH) {
        hv = *reinterpret_cast<const float4*>(d_h + (size_t)src * D_ + d4);
    } else {
        float4 p  = *reinterpret_cast<const float4*>(d_hpre + (size_t)src * D_ + d4);
        float4 sc = *reinterpret_cast<const float4*>(d_sc2 + d4);
        float4 sh = *reinterpret_cast<const float4*>(d_sh2 + d4);
        hv.x = fmaxf(fmaf(p.x, sc.x, sh.x), 0.f);
        hv.y = fmaxf(fmaf(p.y, sc.y, sh.y), 0.f);
        hv.z = fmaxf(fmaf(p.z, sc.z, sh.z), 0.f);
        hv.w = fmaxf(fmaf(p.w, sc.w, sh.w), 0.f);
    }
    float4 m;
    m.x = fmaxf(hv.x + t0.x + t1.x + t2.x, 0.f);
    m.y = fmaxf(hv.y + t0.y + t1.y + t2.y, 0.f);
    m.z = fmaxf(hv.z + t0.z + t1.z + t2.z, 0.f);
    m.w = fmaxf(hv.w + t0.w + t1.w + t2.w, 0.f);
    red4(d_agg + (size_t)dst * D_ + d4, m);
}

// y = act(hpre*sc2+sh2) with sc2/sh2 computed in-kernel from stats;
// hsum += y; agg = (1+eps[lnext])*y   (or final pool on last layer).
// block = 256 threads over float4 elements.
__global__ void k_apply(int do_relu, const float* __restrict__ eps, int lnext,
                        const int* __restrict__ batch, int statOff,
                        const float* __restrict__ g, const float* __restrict__ b,
                        float invM) {
    __shared__ float s_sc[D_], s_sh[D_];
    int tid = threadIdx.x;
    if (tid < D_) {
        const float* st = d_stats + statOff;
        float mean = st[tid] * invM;
        float var  = st[D_ + tid] * invM - mean * mean;
        float is   = rsqrtf(var + 1e-5f);
        float sc   = g[tid] * is;
        float sh   = b[tid] - mean * sc;
        s_sc[tid] = sc; s_sh[tid] = sh;
        if (blockIdx.x == 0) { d_sc2[tid] = sc; d_sh2[tid] = sh; }
    }
    __syncthreads();

    int i = blockIdx.x * blockDim.x + tid;
    float4 p  = reinterpret_cast<const float4*>(d_hpre)[i];
    int c4 = i & 31;
    float4 sc = reinterpret_cast<const float4*>(s_sc)[c4];
    float4 sh = reinterpret_cast<const float4*>(s_sh)[c4];
    float4 y;
    y.x = fmaf(p.x, sc.x, sh.x);
    y.y = fmaf(p.y, sc.y, sh.y);
    y.z = fmaf(p.z, sc.z, sh.z);
    y.w = fmaf(p.w, sc.w, sh.w);
    if (do_relu) {
        y.x = fmaxf(y.x, 0.f); y.y = fmaxf(y.y, 0.f);
        y.z = fmaxf(y.z, 0.f); y.w = fmaxf(y.w, 0.f);
    }
    float4 hs = reinterpret_cast<const float4*>(d_hsum)[i];
    hs.x += y.x; hs.y += y.y; hs.z += y.z; hs.w += y.w;
    if (lnext < L_) {
        reinterpret_cast<float4*>(d_hsum)[i] = hs;
        float s = 1.f + eps[lnext];
        float4 o;
        o.x = y.x * s; o.y = y.y * s; o.z = y.z * s; o.w = y.w * s;
        reinterpret_cast<float4*>(d_agg)[i] = o;
    } else {
        int node = i >> 5;
        int q = i & 31;
        int gr = batch[node];
        red4(d_pool + (size_t)gr * D_ + q * 4, hs);
        if (q == 0) atomicAdd(&d_cnt[gr], 1.f);
    }
}

__global__ void k_rep() {
    int i = blockIdx.x * blockDim.x + threadIdx.x;
    float c = d_cnt[i >> 7];
    d_rep[i] = d_pool[i] / fmaxf(c, 1.f);
}

__global__ void k_initbias(int id, const float* __restrict__ bias, int C, int n) {
    int i = blockIdx.x * blockDim.x + threadIdx.x;
    if (i < n) buf(id)[i] = bias[i % C];
}

__global__ void k_fc4(const float* __restrict__ w4, const float* __restrict__ b4,
                      float* __restrict__ out) {
    int g = blockIdx.x;
    int t = threadIdx.x;
    float acc = 0.f;
#pragma unroll
    for (int k = t; k < 512; k += 128)
        acc += fmaxf(d_zf3[(size_t)g * 512 + k], 0.f) * w4[k];
#pragma unroll
    for (int o = 16; o > 0; o >>= 1)
        acc += __shfl_down_sync(0xffffffffu, acc, o);
    __shared__ float sred[4];
    if ((t & 31) == 0) sred[t >> 5] = acc;
    __syncthreads();
    if (t == 0) out[g] = sred[0] + sred[1] + sred[2] + sred[3] + b4[0];
}

// ---------------- fused tensor-core GEMM (mma.sync, split bf16) ------------
// C[M,Nc] = xform(A_fp32[M,K]) @ W^T + bias.
// XF=0: identity. XF=2: relu(a*sc1[k]+sh1[k]), with sc1/sh1 computed PER-CTA
// from d_stats[statOffIn] + (g,b) — fuses the BN finalize of the previous GEMM.
// STATS: column sum/sumsq of C accumulated into d_stats[statOffOut].
static constexpr int SSTR = 40;   // smem row stride in bf16 elems (80 B)

template <int XF, bool STATS>
__global__ __launch_bounds__(256)
void k_mma(int aId, int wBase, const float* __restrict__ bias, int cId,
           int M, int Nc, int K, int statOffOut,
           int statOffIn, const float* __restrict__ g, const float* __restrict__ b,
           float invM) {
    __shared__ __nv_bfloat16 As_h[128 * SSTR];
    __shared__ __nv_bfloat16 As_l[128 * SSTR];
    __shared__ __nv_bfloat16 Bs_h[128 * SSTR];
    __shared__ __nv_bfloat16 Bs_l[128 * SSTR];
    __shared__ float s_st[256];
    __shared__ float s_sc1[256], s_sh1[256];

    const float* A = buf(aId);
    const int tid = threadIdx.x, lane = tid & 31, wid = tid >> 5;
    const int wm = wid >> 2, wn = wid & 3;           // 2 x 4 warp grid
    const int mblk = blockIdx.y, nblk = blockIdx.x;

    if (XF == 2) {
        // fused finalize of previous BN: K entries (K == 256 here, tid covers all)
        if (tid < K) {
            const float* st = d_stats + statOffIn;
            float mean = st[tid] * invM;
            float var  = st[K + tid] * invM - mean * mean;
            float is   = rsqrtf(var + 1e-5f);
            float sc   = g[tid] * is;
            s_sc1[tid] = sc;
            s_sh1[tid] = b[tid] - mean * sc;
        }
        __syncthreads();
    }

    float acc[4][4][4];
#pragma unroll
    for (int a = 0; a < 4; a++)
#pragma unroll
        for (int bq = 0; bq < 4; bq++)
#pragma unroll
            for (int c = 0; c < 4; c++) acc[a][bq][c] = 0.f;

    const uint32_t sAh = smem_u32(As_h), sAl = smem_u32(As_l);
    const uint32_t sBh = smem_u32(Bs_h), sBl = smem_u32(Bs_l);

    const int aoffb = ((lane & 15) * SSTR + ((lane >> 4) << 3)) * 2;
    const int piece = lane >> 3;
    const int boffb = (((lane & 7) + ((piece >> 1) << 3)) * SSTR + ((piece & 1) << 3)) * 2;

    const int nChunks = K >> 5;
    for (int kc = 0; kc < nChunks; kc++) {
#pragma unroll
        for (int it = 0; it < 2; it++) {
            int idx = it * 256 + tid;
            int r = idx >> 2;
            int c8 = (idx & 3) << 3;
            int gr = mblk * 128 + r;
            int gc = kc * 32 + c8;
            int soff = r * SSTR + c8;
            float v[8];
#pragma unroll
            for (int j = 0; j < 8; j++) v[j] = 0.f;
            if (gr < M) {
                const float4* s = reinterpret_cast<const float4*>(A + (size_t)gr * K + gc);
                *reinterpret_cast<float4*>(v)     = s[0];
                *reinterpret_cast<float4*>(v + 4) = s[1];
            }
            if (XF == 2) {
#pragma unroll
                for (int j = 0; j < 8; j++)
                    v[j] = fmaxf(fmaf(v[j], s_sc1[gc + j], s_sh1[gc + j]), 0.f);
            }
            uint4 uh, ul;
            split8(v, uh, ul);
            *reinterpret_cast<uint4*>(&As_h[soff]) = uh;
            *reinterpret_cast<uint4*>(&As_l[soff]) = ul;
            size_t boff = (size_t)wBase + (size_t)(nblk * 128 + r) * K + gc;
            *reinterpret_cast<uint4*>(&Bs_h[soff]) = *reinterpret_cast<const uint4*>(d_Wh + boff);
            *reinterpret_cast<uint4*>(&Bs_l[soff]) = *reinterpret_cast<const uint4*>(d_Wl + boff);
        }
        __syncthreads();

#pragma unroll
        for (int ks = 0; ks < 2; ks++) {
            const int kb = ks * 32;
            uint32_t a_h[4][4], a_l[4][4], b_h[4][2], b_l[4][2];
#pragma unroll
            for (int mi = 0; mi < 4; mi++) {
                int off = aoffb + kb + (wm * 64 + mi * 16) * (SSTR * 2);
                ldmx4(a_h[mi], sAh + off);
                ldmx4(a_l[mi], sAl + off);
            }
#pragma unroll
            for (int nj = 0; nj < 2; nj++) {
                int off = boffb + kb + (wn * 32 + nj * 16) * (SSTR * 2);
                uint32_t r4[4];
                ldmx4(r4, sBh + off);
                b_h[nj * 2][0] = r4[0]; b_h[nj * 2][1] = r4[1];
                b_h[nj * 2 + 1][0] = r4[2]; b_h[nj * 2 + 1][1] = r4[3];
                ldmx4(r4, sBl + off);
                b_l[nj * 2][0] = r4[0]; b_l[nj * 2][1] = r4[1];
                b_l[nj * 2 + 1][0] = r4[2]; b_l[nj * 2 + 1][1] = r4[3];
            }
#pragma unroll
            for (int mi = 0; mi < 4; mi++)
#pragma unroll
                for (int ni = 0; ni < 4; ni++) {
                    mma_bf16(acc[mi][ni], a_h[mi], b_h[ni]);
                    mma_bf16(acc[mi][ni], a_h[mi], b_l[ni]);
                    mma_bf16(acc[mi][ni], a_l[mi], b_h[ni]);
                }
        }
        __syncthreads();
    }

    // ---- epilogue: bias + store + optional fused column stats ----
    float* C = buf(cId);
    float st_s[8], st_q[8];
#pragma unroll
    for (int j = 0; j < 8; j++) { st_s[j] = 0.f; st_q[j] = 0.f; }

#pragma unroll
    for (int mi = 0; mi < 4; mi++) {
        int row0 = mblk * 128 + wm * 64 + mi * 16 + (lane >> 2);
#pragma unroll
        for (int ni = 0; ni < 4; ni++) {
            int col = nblk * 128 + wn * 32 + ni * 8 + ((lane & 3) << 1);
            float b0 = bias[col], b1 = bias[col + 1];
            float v0 = acc[mi][ni][0] + b0, v1 = acc[mi][ni][1] + b1;
            float v2 = acc[mi][ni][2] + b0, v3 = acc[mi][ni][3] + b1;
            if (row0 < M) {
                *reinterpret_cast<float2*>(&C[(size_t)row0 * Nc + col]) = make_float2(v0, v1);
                if (STATS) {
                    st_s[ni * 2]     += v0; st_q[ni * 2]     += v0 * v0;
                    st_s[ni * 2 + 1] += v1; st_q[ni * 2 + 1] += v1 * v1;
                }
            }
            if (row0 + 8 < M) {
                *reinterpret_cast<float2*>(&C[(size_t)(row0 + 8) * Nc + col]) = make_float2(v2, v3);
                if (STATS) {
                    st_s[ni * 2]     += v2; st_q[ni * 2]     += v2 * v2;
                    st_s[ni * 2 + 1] += v3; st_q[ni * 2 + 1] += v3 * v3;
                }
            }
        }
    }

    if constexpr (STATS) {
        __syncthreads();
        s_st[tid] = 0.f;
        __syncthreads();
#pragma unroll
        for (int j = 0; j < 8; j++) {
            int colLocal = wn * 32 + (j >> 1) * 8 + ((lane & 3) << 1) + (j & 1);
            atomicAdd(&s_st[colLocal], st_s[j]);
            atomicAdd(&s_st[128 + colLocal], st_q[j]);
        }
        __syncthreads();
        if (tid < 128) {
            atomicAdd(&d_stats[statOffOut + nblk * 128 + tid], s_st[tid]);
            atomicAdd(&d_stats[statOffOut + Nc + nblk * 128 + tid], s_st[128 + tid]);
        }
    }
}

// ---------------- FFMA2 SGEMM (FC head only) ----------------
template <int BM, int BN, int BK, int TM, int TN, int XF, bool ATOMIC>
__launch_bounds__((BM / TM) * (BN / TN))
__global__ void k_sgemm(int aId, const float* __restrict__ W,
                        const float* __restrict__ bias, int cId,
                        int M, int K, int Nc, int kLen) {
    constexpr int THREADS = (BM / TM) * (BN / TN);
    constexpr int PAD = 4;
    __shared__ float As[BK][BM + PAD];
    __shared__ float Ws[BK][BN];

    const float* A = buf(aId);
    float* C = buf(cId);

    const int tid  = threadIdx.x;
    const int tcol = tid % (BN / TN);
    const int trow = tid / (BN / TN);
    const int rowBase = blockIdx.y * BM;
    const int colBase = blockIdx.x * BN;
    const int kStart  = blockIdx.z * kLen;

    u64 acc2[TM / 2][TN];
#pragma unroll
    for (int i = 0; i < TM / 2; i++)
#pragma unroll
        for (int j = 0; j < TN; j++) acc2[i][j] = 0ull;

    constexpr int AROWS_PER   = (BM * BK) / THREADS;
    constexpr int AROW_STRIDE = THREADS / BK;
    constexpr int WROWS_PER   = (BK * BN) / THREADS;
    constexpr int WROW_STRIDE = THREADS / BN;

    const int aCol = tid % BK;
    const int aRow = tid / BK;
    const int wCol = tid % BN;
    const int wRow = tid / BN;

    for (int k0 = kStart; k0 < kStart + kLen; k0 += BK) {
        const int kk = k0 + aCol;
#pragma unroll
        for (int r = 0; r < AROWS_PER; r++) {
            int row = rowBase + aRow + r * AROW_STRIDE;
            float v = (row < M) ? A[(size_t)row * K + kk] : 0.f;
            if (XF == 1) v = fmaxf(v, 0.f);
            As[aCol][aRow + r * AROW_STRIDE] = v;
        }
#pragma unroll
        for (int r = 0; r < WROWS_PER; r++) {
            Ws[wRow + r * WROW_STRIDE][wCol] =
                W[(size_t)(k0 + wRow + r * WROW_STRIDE) * Nc + colBase + wCol];
        }
        __syncthreads();
#pragma unroll
        for (int kq = 0; kq < BK; kq++) {
            u64 a2[TM / 2];
            const u64* ap = reinterpret_cast<const u64*>(&As[kq][trow * TM]);
#pragma unroll
            for (int i = 0; i < TM / 2; i++) a2[i] = ap[i];
            float4 wv = *reinterpret_cast<const float4*>(&Ws[kq][tcol * TN]);
            float wf[4] = {wv.x, wv.y, wv.z, wv.w};
#pragma unroll
            for (int j = 0; j < TN; j++) {
                u64 wp = splat2(wf[j]);
#pragma unroll
                for (int i = 0; i < TM / 2; i++) fma2(acc2[i][j], a2[i], wp);
            }
        }
        __syncthreads();
    }

#pragma unroll
    for (int i = 0; i < TM / 2; i++) {
        int row0 = rowBase + trow * TM + 2 * i;
        float lo[TN], hi[TN];
#pragma unroll
        for (int j = 0; j < TN; j++) unpack2(acc2[i][j], lo[j], hi[j]);
        int col0 = colBase + tcol * TN;
        if (ATOMIC) {
            if (row0 < M) {
#pragma unroll
                for (int j = 0; j < TN; j++) atomicAdd(&C[(size_t)row0 * Nc + col0 + j], lo[j]);
            }
            if (row0 + 1 < M) {
#pragma unroll
                for (int j = 0; j < TN; j++) atomicAdd(&C[(size_t)(row0 + 1) * Nc + col0 + j], hi[j]);
            }
        } else {
            float bc[TN];
#pragma unroll
            for (int j = 0; j < TN; j++) bc[j] = bias[col0 + j];
            if (row0 < M) {
#pragma unroll
                for (int j = 0; j < TN; j++) C[(size_t)row0 * Nc + col0 + j] = lo[j] + bc[j];
            }
            if (row0 + 1 < M) {
#pragma unroll
                for (int j = 0; j < TN; j++) C[(size_t)(row0 + 1) * Nc + col0 + j] = hi[j] + bc[j];
            }
        }
    }
}

// ---------------- launch ----------------
extern "C" void kernel_launch(void* const* d_in, const int* in_sizes, int n_in,
                              void* d_out, int out_size) {
    const int*   x        = (const int*)  d_in[0];
    const int*   ei       = (const int*)  d_in[1];
    const int*   ea       = (const int*)  d_in[2];
    const int*   batch    = (const int*)  d_in[3];
    const float* atom_emb = (const float*)d_in[4];
    const float* bond_emb = (const float*)d_in[5];
    const float* eps      = (const float*)d_in[6];
    const float* W1       = (const float*)d_in[7];
    const float* b1       = (const float*)d_in[8];
    const float* g1       = (const float*)d_in[9];
    const float* be1      = (const float*)d_in[10];
    const float* W2       = (const float*)d_in[11];
    const float* b2       = (const float*)d_in[12];
    const float* bn_g     = (const float*)d_in[13];
    const float* bn_b     = (const float*)d_in[14];
    const float* fcW1     = (const float*)d_in[15];
    const float* fcb1     = (const float*)d_in[16];
    const float* fcW2     = (const float*)d_in[17];
    const float* fcb2     = (const float*)d_in[18];
    const float* fcW3     = (const float*)d_in[19];
    const float* fcb3     = (const float*)d_in[20];
    const float* fcW4     = (const float*)d_in[21];
    const float* fcb4     = (const float*)d_in[22];
    float* out = (float*)d_out;

    const float invN = 1.f / (float)N_;

    // setup: one zero launch, one weight-convert launch, atom encoder
    k_zero_all<<<(L_ * 1024 + G_ * D_ + G_ + 255) / 256, 256>>>();
    k_cvtW2<<<(8192 + 255) / 256, 256>>>(W1, W2);
    k_atom<<<N_, 128>>>(x, atom_emb, eps);

    const int vec = N_ * D_ / 4;
    for (int l = 0; l < L_; l++) {
        // scatter: agg += relu(h[src] + bond)  (h recomputed from hpre for l>0)
        k_edge<<<E_ / 8, 256>>>(ei, ea, bond_emb + (size_t)l * 3 * V_ * D_, l == 0 ? 1 : 0);

        // GEMM1: z1 = agg @ W1 + b1  [N,128]x[128,256], fused column stats
        k_mma<0, true><<<dim3(2, MBLKS), 256>>>(2, 0, b1, 3, N_, 256, 128,
                                                l * 1024, 0, nullptr, nullptr, 0.f);

        // GEMM2: hpre = relu(bn1(z1)) @ W2 + b2, bn1 finalize fused in-CTA
        k_mma<2, true><<<dim3(1, MBLKS), 256>>>(3, 32768, b2, 4, N_, 128, 256,
                                                l * 1024 + 512, l * 1024, g1, be1, invN);

        // bn2 finalize fused; h recompute params persisted; hsum/agg (or pool)
        k_apply<<<vec / 256, 256>>>(l < L_ - 1 ? 1 : 0, eps, l + 1, batch,
                                    l * 1024 + 512, bn_g + l * D_, bn_b + l * D_, invN);
    }

    // readout
    k_rep<<<(G_ * D_) / 256, 256>>>();

    // FC head
    k_sgemm<64, 64, 16, 4, 4, 0, false>
        <<<dim3(1024 / 64, G_ / 64, 1), 256>>>(12, fcW1, fcb1, 13, G_, 128, 1024, 128);

    k_initbias<<<(G_ * 1024) / 256, 256>>>(14, fcb2, 1024, G_ * 1024);
    k_sgemm<64, 64, 16, 4, 4, 1, true>
        <<<dim3(1024 / 64, G_ / 64, 8), 256>>>(13, fcW2, nullptr, 14, G_, 1024, 1024, 128);

    k_initbias<<<(G_ * 512) / 256, 256>>>(15, fcb3, 512, G_ * 512);
    k_sgemm<64, 64, 16, 4, 4, 1, true>
        <<<dim3(512 / 64, G_ / 64, 8), 256>>>(14, fcW3, nullptr, 15, G_, 1024, 512, 128);

    k_fc4<<<G_, 128>>>(fcW4, fcb4, out);
}

// round 10
// speedup vs baseline: 1.0483x; 1.0415x over previous
#include <cuda_runtime.h>
#include <cuda_bf16.h>
#include <cstdint>

// ---------------- problem constants ----------------
static constexpr int N_ = 50000;
static constexpr int E_ = 600000;
static constexpr int G_ = 256;
static constexpr int D_ = 128;
static constexpr int L_ = 5;
static constexpr int V_ = 128;

static constexpr int MBLKS = (N_ + 127) / 128;   // 391

// ---------------- scratch (static device globals; no runtime alloc) --------
__device__ float d_h   [N_ * D_];     // layer-0 input (atom encoder output)
__device__ float d_hsum[N_ * D_];
__device__ float d_agg [N_ * D_];
__device__ float d_z1  [N_ * 2 * D_];
__device__ float d_hpre[N_ * D_];
__device__ float d_stats[L_ * 1024];
__device__ float d_sc2[D_];
__device__ float d_sh2[D_];
__device__ float d_pool[G_ * D_];
__device__ float d_cnt [G_];
__device__ float d_rep [G_ * D_];
__device__ float d_zf1 [G_ * 1024];
__device__ float d_zf2 [G_ * 1024];
__device__ float d_zf3 [G_ * 512];

// CSR edge structures (built once per call; edges identical across layers)
__device__ int  d_deg   [N_];
__device__ int  d_rowptr[N_ + 1];
__device__ int  d_woff  [N_];
__device__ int4 d_epack [E_];        // {src, a0, a1, a2} in dst-sorted order

// bf16 split weights (row-major W^T)
__device__ __nv_bfloat16 d_Wh[65536];       // W1^T [256,128] @0, W2^T [128,256] @32768
__device__ __nv_bfloat16 d_Wl[65536];

__device__ __forceinline__ float* buf(int id) {
    switch (id) {
        case 0:  return d_h;
        case 1:  return d_hsum;
        case 2:  return d_agg;
        case 3:  return d_z1;
        case 4:  return d_hpre;
        case 5:  return d_stats;
        case 10: return d_pool;
        case 11: return d_cnt;
        case 12: return d_rep;
        case 13: return d_zf1;
        case 14: return d_zf2;
        case 15: return d_zf3;
    }
    return nullptr;
}

// ---------------- PTX helpers ----------------
typedef unsigned long long u64;

__device__ __forceinline__ uint32_t smem_u32(const void* p) {
    uint32_t a;
    asm("{ .reg .u64 t; cvta.to.shared.u64 t, %1; cvt.u32.u64 %0, t; }" : "=r"(a) : "l"(p));
    return a;
}
__device__ __forceinline__ void mma_bf16(float* d, const uint32_t* a, const uint32_t* b) {
    asm volatile(
        "mma.sync.aligned.m16n8k16.row.col.f32.bf16.bf16.f32 "
        "{%0,%1,%2,%3}, {%4,%5,%6,%7}, {%8,%9}, {%0,%1,%2,%3};"
        : "+f"(d[0]), "+f"(d[1]), "+f"(d[2]), "+f"(d[3])
        : "r"(a[0]), "r"(a[1]), "r"(a[2]), "r"(a[3]), "r"(b[0]), "r"(b[1]));
}
__device__ __forceinline__ void ldmx4(uint32_t* r, uint32_t addr) {
    asm volatile("ldmatrix.sync.aligned.m8n8.x4.shared.b16 {%0,%1,%2,%3}, [%4];"
                 : "=r"(r[0]), "=r"(r[1]), "=r"(r[2]), "=r"(r[3]) : "r"(addr));
}

// split 8 floats into bf16 hi + lo packs
__device__ __forceinline__ void split8(const float* v, uint4& uh, uint4& ul) {
    __nv_bfloat16 h[8], l[8];
#pragma unroll
    for (int j = 0; j < 8; j++) {
        float x = v[j];
        __nv_bfloat16 hb = __float2bfloat16(x);
        h[j] = hb;
        l[j] = __float2bfloat16(x - __bfloat162float(hb));
    }
    uh = *reinterpret_cast<uint4*>(h);
    ul = *reinterpret_cast<uint4*>(l);
}

// f32x2 packed helpers (FC head SGEMM)
__device__ __forceinline__ u64 splat2(float x) {
    u64 r; asm("mov.b64 %0, {%1, %1};" : "=l"(r) : "f"(x)); return r;
}
__device__ __forceinline__ void fma2(u64& d, u64 a, u64 b) {
    asm("fma.rn.f32x2 %0, %1, %2, %0;" : "+l"(d) : "l"(a), "l"(b));
}
__device__ __forceinline__ void unpack2(u64 p, float& lo, float& hi) {
    asm("mov.b64 {%0, %1}, %2;" : "=f"(lo), "=f"(hi) : "l"(p));
}
__device__ __forceinline__ void red4(float* addr, float4 v) {
    asm volatile("red.global.add.v4.f32 [%0], {%1,%2,%3,%4};"
                 :: "l"(addr), "f"(v.x), "f"(v.y), "f"(v.z), "f"(v.w) : "memory");
}

// ---------------- setup kernels ----------------
// zero stats + pool + cnt + deg in one launch
__global__ void k_zero_all() {
    int i = blockIdx.x * blockDim.x + threadIdx.x;
    int o = i;
    if (o < L_ * 1024) { d_stats[o] = 0.f; return; }
    o -= L_ * 1024;
    if (o < G_ * D_) { d_pool[o] = 0.f; return; }
    o -= G_ * D_;
    if (o < G_) { d_cnt[o] = 0.f; return; }
    o -= G_;
    if (o < N_) d_deg[o] = 0;
}

// histogram of dst
__global__ void k_hist(const int* __restrict__ ei) {
    int e = blockIdx.x * blockDim.x + threadIdx.x;
    if (e < E_) atomicAdd(&d_deg[ei[E_ + e]], 1);
}

// single-block exclusive scan of d_deg -> d_rowptr, d_woff
__global__ void k_scan() {
    __shared__ int part[1024];
    int t = threadIdx.x;
    const int C = (N_ + 1023) / 1024;   // 49
    int lo = t * C, hi = min(lo + C, N_);
    int s = 0;
    for (int i = lo; i < hi; i++) s += d_deg[i];
    part[t] = s;
    __syncthreads();
    for (int off = 1; off < 1024; off <<= 1) {
        int v = (t >= off) ? part[t - off] : 0;
        __syncthreads();
        part[t] += v;
        __syncthreads();
    }
    int run = part[t] - s;   // exclusive prefix for this chunk
    for (int i = lo; i < hi; i++) {
        d_rowptr[i] = run;
        d_woff[i]   = run;
        run += d_deg[i];
    }
    if (t == 1023) d_rowptr[N_] = E_;
}

// scatter edges into dst-sorted packed form
__global__ void k_scatter(const int* __restrict__ ei, const int* __restrict__ ea) {
    int e = blockIdx.x * blockDim.x + threadIdx.x;
    if (e >= E_) return;
    int dst = ei[E_ + e];
    int pos = atomicAdd(&d_woff[dst], 1);
    d_epack[pos] = make_int4(ei[e], ea[e * 3 + 0], ea[e * 3 + 1], ea[e * 3 + 2]);
}

__global__ void k_atom(const int* __restrict__ x, const float* __restrict__ aemb) {
    int i = blockIdx.x;
    int d = threadIdx.x;
    float v = 0.f;
#pragma unroll
    for (int f = 0; f < 9; f++) {
        int idx = x[i * 9 + f];
        v += aemb[((size_t)f * V_ + idx) * D_ + d];
    }
    d_h[(size_t)i * D_ + d]    = v;
    d_hsum[(size_t)i * D_ + d] = v;
}

// pull-based aggregation: agg[n] = (1+eps[l])*h(n) + sum_{e->n} relu(h(src)+bond(e))
// h(i) = d_h[i] (layer 0) or relu(hpre[i]*sc2+sh2) (layers > 0). Warp per node.
__global__ void k_gather(const float* __restrict__ bond, const float* __restrict__ eps,
                         int l, int useH) {
    int warp = (blockIdx.x * blockDim.x + threadIdx.x) >> 5;
    if (warp >= N_) return;
    int lane = threadIdx.x & 31;
    int d4 = lane * 4;

    float4 sc, sh;
    if (!useH) {
        sc = *reinterpret_cast<const float4*>(d_sc2 + d4);
        sh = *reinterpret_cast<const float4*>(d_sh2 + d4);
    }

    float4 hd;
    if (useH) {
        hd = *reinterpret_cast<const float4*>(d_h + (size_t)warp * D_ + d4);
    } else {
        float4 p = *reinterpret_cast<const float4*>(d_hpre + (size_t)warp * D_ + d4);
        hd.x = fmaxf(fmaf(p.x, sc.x, sh.x), 0.f);
        hd.y = fmaxf(fmaf(p.y, sc.y, sh.y), 0.f);
        hd.z = fmaxf(fmaf(p.z, sc.z, sh.z), 0.f);
        hd.w = fmaxf(fmaf(p.w, sc.w, sh.w), 0.f);
    }
    float s = 1.f + eps[l];
    float4 acc;
    acc.x = s * hd.x; acc.y = s * hd.y; acc.z = s * hd.z; acc.w = s * hd.w;

    int p0 = d_rowptr[warp], p1 = d_rowptr[warp + 1];
    for (int p = p0; p < p1; p++) {
        int4 ep = d_epack[p];
        float4 t0 = *reinterpret_cast<const float4*>(bond + ((size_t)0 * V_ + ep.y) * D_ + d4);
        float4 t1 = *reinterpret_cast<const float4*>(bond + ((size_t)1 * V_ + ep.z) * D_ + d4);
        float4 t2 = *reinterpret_cast<const float4*>(bond + ((size_t)2 * V_ + ep.w) * D_ + d4);
        float4 hv;
        if (useH) {
            hv = *reinterpret_cast<const float4*>(d_h + (size_t)ep.x * D_ + d4);
        } else {
            float4 pp = *reinterpret_cast<const float4*>(d_hpre + (size_t)ep.x * D_ + d4);
            hv.x = fmaxf(fmaf(pp.x, sc.x, sh.x), 0.f);
            hv.y = fmaxf(fmaf(pp.y, sc.y, sh.y), 0.f);
            hv.z = fmaxf(fmaf(pp.z, sc.z, sh.z), 0.f);
            hv.w = fmaxf(fmaf(pp.w, sc.w, sh.w), 0.f);
        }
        acc.x += fmaxf(hv.x + t0.x + t1.x + t2.x, 0.f);
        acc.y += fmaxf(hv.y + t0.y + t1.y + t2.y, 0.f);
        acc.z += fmaxf(hv.z + t0.z + t1.z + t2.z, 0.f);
        acc.w += fmaxf(hv.w + t0.w + t1.w + t2.w, 0.f);
    }
    *reinterpret_cast<float4*>(d_agg + (size_t)warp * D_ + d4) = acc;
}

// y = act(hpre*sc2+sh2) with sc2/sh2 computed in-kernel from stats;
// hsum += y (or final pool on last layer). sc2/sh2 persisted for k_gather.
__global__ void k_apply(int do_relu, int lnext, const int* __restrict__ batch,
                        int statOff, const float* __restrict__ g,
                        const float* __restrict__ b, float invM) {
    __shared__ float s_sc[D_], s_sh[D_];
    int tid = threadIdx.x;
    if (tid < D_) {
        const float* st = d_stats + statOff;
        float mean = st[tid] * invM;
        float var  = st[D_ + tid] * invM - mean * mean;
        float is   = rsqrtf(var + 1e-5f);
        float sc   = g[tid] * is;
        float sh   = b[tid] - mean * sc;
        s_sc[tid] = sc; s_sh[tid] = sh;
        if (blockIdx.x == 0) { d_sc2[tid] = sc; d_sh2[tid] = sh; }
    }
    __syncthreads();

    int i = blockIdx.x * blockDim.x + tid;
    float4 p  = reinterpret_cast<const float4*>(d_hpre)[i];
    int c4 = i & 31;
    float4 sc = reinterpret_cast<const float4*>(s_sc)[c4];
    float4 sh = reinterpret_cast<const float4*>(s_sh)[c4];
    float4 y;
    y.x = fmaf(p.x, sc.x, sh.x);
    y.y = fmaf(p.y, sc.y, sh.y);
    y.z = fmaf(p.z, sc.z, sh.z);
    y.w = fmaf(p.w, sc.w, sh.w);
    if (do_relu) {
        y.x = fmaxf(y.x, 0.f); y.y = fmaxf(y.y, 0.f);
        y.z = fmaxf(y.z, 0.f); y.w = fmaxf(y.w, 0.f);
    }
    float4 hs = reinterpret_cast<const float4*>(d_hsum)[i];
    hs.x += y.x; hs.y += y.y; hs.z += y.z; hs.w += y.w;
    if (lnext < L_) {
        reinterpret_cast<float4*>(d_hsum)[i] = hs;
    } else {
        int node = i >> 5;
        int q = i & 31;
        int gr = batch[node];
        red4(d_pool + (size_t)gr * D_ + q * 4, hs);
        if (q == 0) atomicAdd(&d_cnt[gr], 1.f);
    }
}

__global__ void k_rep() {
    int i = blockIdx.x * blockDim.x + threadIdx.x;
    float c = d_cnt[i >> 7];
    d_rep[i] = d_pool[i] / fmaxf(c, 1.f);
}

__global__ void k_initbias(int id, const float* __restrict__ bias, int C, int n) {
    int i = blockIdx.x * blockDim.x + threadIdx.x;
    if (i < n) buf(id)[i] = bias[i % C];
}

__global__ void k_fc4(const float* __restrict__ w4, const float* __restrict__ b4,
                      float* __restrict__ out) {
    int g = blockIdx.x;
    int t = threadIdx.x;
    float acc = 0.f;
#pragma unroll
    for (int k = t; k < 512; k += 128)
        acc += fmaxf(d_zf3[(size_t)g * 512 + k], 0.f) * w4[k];
#pragma unroll
    for (int o = 16; o > 0; o >>= 1)
        acc += __shfl_down_sync(0xffffffffu, acc, o);
    __shared__ float sred[4];
    if ((t & 31) == 0) sred[t >> 5] = acc;
    __syncthreads();
    if (t == 0) out[g] = sred[0] + sred[1] + sred[2] + sred[3] + b4[0];
}

// both weights split/transposed in one launch
__global__ void k_cvtW2(const float* __restrict__ W1, const float* __restrict__ W2) {
    int idx = blockIdx.x * blockDim.x + threadIdx.x;
    const float* W; int K, Nc, wBase;
    if (idx < 4096)      { W = W1; K = 128; Nc = 256; wBase = 0; }
    else if (idx < 8192) { W = W2; K = 256; Nc = 128; wBase = 32768; idx -= 4096; }
    else return;
    int n  = idx / (K >> 3);
    int k0 = (idx % (K >> 3)) << 3;
    float v[8];
#pragma unroll
    for (int j = 0; j < 8; j++) v[j] = W[(size_t)(k0 + j) * Nc + n];
    uint4 uh, ul;
    split8(v, uh, ul);
    size_t o = ((size_t)wBase + (size_t)n * K + k0) >> 3;
    reinterpret_cast<uint4*>(d_Wh)[o] = uh;
    reinterpret_cast<uint4*>(d_Wl)[o] = ul;
}

// ---------------- fused tensor-core GEMM (mma.sync, split bf16) ------------
static constexpr int SSTR = 40;   // smem row stride in bf16 elems (80 B)

template <int XF, bool STATS>
__global__ __launch_bounds__(256)
void k_mma(int aId, int wBase, const float* __restrict__ bias, int cId,
           int M, int Nc, int K, int statOffOut,
           int statOffIn, const float* __restrict__ g, const float* __restrict__ b,
           float invM) {
    __shared__ __nv_bfloat16 As_h[128 * SSTR];
    __shared__ __nv_bfloat16 As_l[128 * SSTR];
    __shared__ __nv_bfloat16 Bs_h[128 * SSTR];
    __shared__ __nv_bfloat16 Bs_l[128 * SSTR];
    __shared__ float s_st[256];
    __shared__ float s_sc1[256], s_sh1[256];

    const float* A = buf(aId);
    const int tid = threadIdx.x, lane = tid & 31, wid = tid >> 5;
    const int wm = wid >> 2, wn = wid & 3;
    const int mblk = blockIdx.y, nblk = blockIdx.x;

    if (XF == 2) {
        if (tid < K) {
            const float* st = d_stats + statOffIn;
            float mean = st[tid] * invM;
            float var  = st[K + tid] * invM - mean * mean;
            float is   = rsqrtf(var + 1e-5f);
            float sc   = g[tid] * is;
            s_sc1[tid] = sc;
            s_sh1[tid] = b[tid] - mean * sc;
        }
        __syncthreads();
    }

    float acc[4][4][4];
#pragma unroll
    for (int a = 0; a < 4; a++)
#pragma unroll
        for (int bq = 0; bq < 4; bq++)
#pragma unroll
            for (int c = 0; c < 4; c++) acc[a][bq][c] = 0.f;

    const uint32_t sAh = smem_u32(As_h), sAl = smem_u32(As_l);
    const uint32_t sBh = smem_u32(Bs_h), sBl = smem_u32(Bs_l);

    const int aoffb = ((lane & 15) * SSTR + ((lane >> 4) << 3)) * 2;
    const int piece = lane >> 3;
    const int boffb = (((lane & 7) + ((piece >> 1) << 3)) * SSTR + ((piece & 1) << 3)) * 2;

    const int nChunks = K >> 5;
    for (int kc = 0; kc < nChunks; kc++) {
#pragma unroll
        for (int it = 0; it < 2; it++) {
            int idx = it * 256 + tid;
            int r = idx >> 2;
            int c8 = (idx & 3) << 3;
            int gr = mblk * 128 + r;
            int gc = kc * 32 + c8;
            int soff = r * SSTR + c8;
            float v[8];
#pragma unroll
            for (int j = 0; j < 8; j++) v[j] = 0.f;
            if (gr < M) {
                const float4* s = reinterpret_cast<const float4*>(A + (size_t)gr * K + gc);
                *reinterpret_cast<float4*>(v)     = s[0];
                *reinterpret_cast<float4*>(v + 4) = s[1];
            }
            if (XF == 2) {
#pragma unroll
                for (int j = 0; j < 8; j++)
                    v[j] = fmaxf(fmaf(v[j], s_sc1[gc + j], s_sh1[gc + j]), 0.f);
            }
            uint4 uh, ul;
            split8(v, uh, ul);
            *reinterpret_cast<uint4*>(&As_h[soff]) = uh;
            *reinterpret_cast<uint4*>(&As_l[soff]) = ul;
            size_t boff = (size_t)wBase + (size_t)(nblk * 128 + r) * K + gc;
            *reinterpret_cast<uint4*>(&Bs_h[soff]) = *reinterpret_cast<const uint4*>(d_Wh + boff);
            *reinterpret_cast<uint4*>(&Bs_l[soff]) = *reinterpret_cast<const uint4*>(d_Wl + boff);
        }
        __syncthreads();

#pragma unroll
        for (int ks = 0; ks < 2; ks++) {
            const int kb = ks * 32;
            uint32_t a_h[4][4], a_l[4][4], b_h[4][2], b_l[4][2];
#pragma unroll
            for (int mi = 0; mi < 4; mi++) {
                int off = aoffb + kb + (wm * 64 + mi * 16) * (SSTR * 2);
                ldmx4(a_h[mi], sAh + off);
                ldmx4(a_l[mi], sAl + off);
            }
#pragma unroll
            for (int nj = 0; nj < 2; nj++) {
                int off = boffb + kb + (wn * 32 + nj * 16) * (SSTR * 2);
                uint32_t r4[4];
                ldmx4(r4, sBh + off);
                b_h[nj * 2][0] = r4[0]; b_h[nj * 2][1] = r4[1];
                b_h[nj * 2 + 1][0] = r4[2]; b_h[nj * 2 + 1][1] = r4[3];
                ldmx4(r4, sBl + off);
                b_l[nj * 2][0] = r4[0]; b_l[nj * 2][1] = r4[1];
                b_l[nj * 2 + 1][0] = r4[2]; b_l[nj * 2 + 1][1] = r4[3];
            }
#pragma unroll
            for (int mi = 0; mi < 4; mi++)
#pragma unroll
                for (int ni = 0; ni < 4; ni++) {
                    mma_bf16(acc[mi][ni], a_h[mi], b_h[ni]);
                    mma_bf16(acc[mi][ni], a_h[mi], b_l[ni]);
                    mma_bf16(acc[mi][ni], a_l[mi], b_h[ni]);
                }
        }
        __syncthreads();
    }

    float* C = buf(cId);
    float st_s[8], st_q[8];
#pragma unroll
    for (int j = 0; j < 8; j++) { st_s[j] = 0.f; st_q[j] = 0.f; }

#pragma unroll
    for (int mi = 0; mi < 4; mi++) {
        int row0 = mblk * 128 + wm * 64 + mi * 16 + (lane >> 2);
#pragma unroll
        for (int ni = 0; ni < 4; ni++) {
            int col = nblk * 128 + wn * 32 + ni * 8 + ((lane & 3) << 1);
            float b0 = bias[col], b1 = bias[col + 1];
            float v0 = acc[mi][ni][0] + b0, v1 = acc[mi][ni][1] + b1;
            float v2 = acc[mi][ni][2] + b0, v3 = acc[mi][ni][3] + b1;
            if (row0 < M) {
                *reinterpret_cast<float2*>(&C[(size_t)row0 * Nc + col]) = make_float2(v0, v1);
                if (STATS) {
                    st_s[ni * 2]     += v0; st_q[ni * 2]     += v0 * v0;
                    st_s[ni * 2 + 1] += v1; st_q[ni * 2 + 1] += v1 * v1;
                }
            }
            if (row0 + 8 < M) {
                *reinterpret_cast<float2*>(&C[(size_t)(row0 + 8) * Nc + col]) = make_float2(v2, v3);
                if (STATS) {
                    st_s[ni * 2]     += v2; st_q[ni * 2]     += v2 * v2;
                    st_s[ni * 2 + 1] += v3; st_q[ni * 2 + 1] += v3 * v3;
                }
            }
        }
    }

    if constexpr (STATS) {
        __syncthreads();
        s_st[tid] = 0.f;
        __syncthreads();
#pragma unroll
        for (int j = 0; j < 8; j++) {
            int colLocal = wn * 32 + (j >> 1) * 8 + ((lane & 3) << 1) + (j & 1);
            atomicAdd(&s_st[colLocal], st_s[j]);
            atomicAdd(&s_st[128 + colLocal], st_q[j]);
        }
        __syncthreads();
        if (tid < 128) {
            atomicAdd(&d_stats[statOffOut + nblk * 128 + tid], s_st[tid]);
            atomicAdd(&d_stats[statOffOut + Nc + nblk * 128 + tid], s_st[128 + tid]);
        }
    }
}

// ---------------- FFMA2 SGEMM (FC head only) ----------------
template <int BM, int BN, int BK, int TM, int TN, int XF, bool ATOMIC>
__launch_bounds__((BM / TM) * (BN / TN))
__global__ void k_sgemm(int aId, const float* __restrict__ W,
                        const float* __restrict__ bias, int cId,
                        int M, int K, int Nc, int kLen) {
    constexpr int THREADS = (BM / TM) * (BN / TN);
    constexpr int PAD = 4;
    __shared__ float As[BK][BM + PAD];
    __shared__ float Ws[BK][BN];

    const float* A = buf(aId);
    float* C = buf(cId);

    const int tid  = threadIdx.x;
    const int tcol = tid % (BN / TN);
    const int trow = tid / (BN / TN);
    const int rowBase = blockIdx.y * BM;
    const int colBase = blockIdx.x * BN;
    const int kStart  = blockIdx.z * kLen;

    u64 acc2[TM / 2][TN];
#pragma unroll
    for (int i = 0; i < TM / 2; i++)
#pragma unroll
        for (int j = 0; j < TN; j++) acc2[i][j] = 0ull;

    constexpr int AROWS_PER   = (BM * BK) / THREADS;
    constexpr int AROW_STRIDE = THREADS / BK;
    constexpr int WROWS_PER   = (BK * BN) / THREADS;
    constexpr int WROW_STRIDE = THREADS / BN;

    const int aCol = tid % BK;
    const int aRow = tid / BK;
    const int wCol = tid % BN;
    const int wRow = tid / BN;

    for (int k0 = kStart; k0 < kStart + kLen; k0 += BK) {
        const int kk = k0 + aCol;
#pragma unroll
        for (int r = 0; r < AROWS_PER; r++) {
            int row = rowBase + aRow + r * AROW_STRIDE;
            float v = (row < M) ? A[(size_t)row * K + kk] : 0.f;
            if (XF == 1) v = fmaxf(v, 0.f);
            As[aCol][aRow + r * AROW_STRIDE] = v;
        }
#pragma unroll
        for (int r = 0; r < WROWS_PER; r++) {
            Ws[wRow + r * WROW_STRIDE][wCol] =
                W[(size_t)(k0 + wRow + r * WROW_STRIDE) * Nc + colBase + wCol];
        }
        __syncthreads();
#pragma unroll
        for (int kq = 0; kq < BK; kq++) {
            u64 a2[TM / 2];
            const u64* ap = reinterpret_cast<const u64*>(&As[kq][trow * TM]);
#pragma unroll
            for (int i = 0; i < TM / 2; i++) a2[i] = ap[i];
            float4 wv = *reinterpret_cast<const float4*>(&Ws[kq][tcol * TN]);
            float wf[4] = {wv.x, wv.y, wv.z, wv.w};
#pragma unroll
            for (int j = 0; j < TN; j++) {
                u64 wp = splat2(wf[j]);
#pragma unroll
                for (int i = 0; i < TM / 2; i++) fma2(acc2[i][j], a2[i], wp);
            }
        }
        __syncthreads();
    }

#pragma unroll
    for (int i = 0; i < TM / 2; i++) {
        int row0 = rowBase + trow * TM + 2 * i;
        float lo[TN], hi[TN];
#pragma unroll
        for (int j = 0; j < TN; j++) unpack2(acc2[i][j], lo[j], hi[j]);
        int col0 = colBase + tcol * TN;
        if (ATOMIC) {
            if (row0 < M) {
#pragma unroll
                for (int j = 0; j < TN; j++) atomicAdd(&C[(size_t)row0 * Nc + col0 + j], lo[j]);
            }
            if (row0 + 1 < M) {
#pragma unroll
                for (int j = 0; j < TN; j++) atomicAdd(&C[(size_t)(row0 + 1) * Nc + col0 + j], hi[j]);
            }
        } else {
            float bc[TN];
#pragma unroll
            for (int j = 0; j < TN; j++) bc[j] = bias[col0 + j];
            if (row0 < M) {
#pragma unroll
                for (int j = 0; j < TN; j++) C[(size_t)row0 * Nc + col0 + j] = lo[j] + bc[j];
            }
            if (row0 + 1 < M) {
#pragma unroll
                for (int j = 0; j < TN; j++) C[(size_t)(row0 + 1) * Nc + col0 + j] = hi[j] + bc[j];
            }
        }
    }
}

// ---------------- launch ----------------
extern "C" void kernel_launch(void* const* d_in, const int* in_sizes, int n_in,
                              void* d_out, int out_size) {
    const int*   x        = (const int*)  d_in[0];
    const int*   ei       = (const int*)  d_in[1];
    const int*   ea       = (const int*)  d_in[2];
    const int*   batch    = (const int*)  d_in[3];
    const float* atom_emb = (const float*)d_in[4];
    const float* bond_emb = (const float*)d_in[5];
    const float* eps      = (const float*)d_in[6];
    const float* W1       = (const float*)d_in[7];
    const float* b1       = (const float*)d_in[8];
    const float* g1       = (const float*)d_in[9];
    const float* be1      = (const float*)d_in[10];
    const float* W2       = (const float*)d_in[11];
    const float* b2       = (const float*)d_in[12];
    const float* bn_g     = (const float*)d_in[13];
    const float* bn_b     = (const float*)d_in[14];
    const float* fcW1     = (const float*)d_in[15];
    const float* fcb1     = (const float*)d_in[16];
    const float* fcW2     = (const float*)d_in[17];
    const float* fcb2     = (const float*)d_in[18];
    const float* fcW3     = (const float*)d_in[19];
    const float* fcb3     = (const float*)d_in[20];
    const float* fcW4     = (const float*)d_in[21];
    const float* fcb4     = (const float*)d_in[22];
    float* out = (float*)d_out;

    const float invN = 1.f / (float)N_;

    // setup + CSR build (edges identical across layers)
    k_zero_all<<<(L_ * 1024 + G_ * D_ + G_ + N_ + 255) / 256, 256>>>();
    k_cvtW2<<<(8192 + 255) / 256, 256>>>(W1, W2);
    k_atom<<<N_, 128>>>(x, atom_emb);
    k_hist<<<(E_ + 255) / 256, 256>>>(ei);
    k_scan<<<1, 1024>>>();
    k_scatter<<<(E_ + 255) / 256, 256>>>(ei, ea);

    const int vec = N_ * D_ / 4;
    for (int l = 0; l < L_; l++) {
        // pull aggregation (no atomics): agg = (1+eps)h + sum relu(h[src]+bond)
        k_gather<<<(N_ * 32 + 255) / 256, 256>>>(bond_emb + (size_t)l * 3 * V_ * D_,
                                                 eps, l, l == 0 ? 1 : 0);

        // GEMM1: z1 = agg @ W1 + b1  [N,128]x[128,256], fused column stats
        k_mma<0, true><<<dim3(2, MBLKS), 256>>>(2, 0, b1, 3, N_, 256, 128,
                                                l * 1024, 0, nullptr, nullptr, 0.f);

        // GEMM2: hpre = relu(bn1(z1)) @ W2 + b2, bn1 finalize fused in-CTA
        k_mma<2, true><<<dim3(1, MBLKS), 256>>>(3, 32768, b2, 4, N_, 128, 256,
                                                l * 1024 + 512, l * 1024, g1, be1, invN);

        // bn2 finalize fused; sc2/sh2 persisted for next gather; hsum/pool
        k_apply<<<vec / 256, 256>>>(l < L_ - 1 ? 1 : 0, l + 1, batch,
                                    l * 1024 + 512, bn_g + l * D_, bn_b + l * D_, invN);
    }

    // readout
    k_rep<<<(G_ * D_) / 256, 256>>>();

    // FC head
    k_sgemm<64, 64, 16, 4, 4, 0, false>
        <<<dim3(1024 / 64, G_ / 64, 1), 256>>>(12, fcW1, fcb1, 13, G_, 128, 1024, 128);

    k_initbias<<<(G_ * 1024) / 256, 256>>>(14, fcb2, 1024, G_ * 1024);
    k_sgemm<64, 64, 16, 4, 4, 1, true>
        <<<dim3(1024 / 64, G_ / 64, 8), 256>>>(13, fcW2, nullptr, 14, G_, 1024, 1024, 128);

    k_initbias<<<(G_ * 512) / 256, 256>>>(15, fcb3, 512, G_ * 512);
    k_sgemm<64, 64, 16, 4, 4, 1, true>
        <<<dim3(512 / 64, G_ / 64, 8), 256>>>(14, fcW3, nullptr, 15, G_, 1024, 512, 128);

    k_fc4<<<G_, 128>>>(fcW4, fcb4, out);
}